// round 2
// baseline (speedup 1.0000x reference)
#include <cuda_runtime.h>
#include <math.h>

#define BB 16
#define SEQ 4107
#define NTOK 4096
#define DIMD 768
#define LATD 20
#define NP 10
#define NROWS_X (BB*SEQ)
#define NROWS_L (BB*NTOK)

// ---------------- scratch (device globals: no allocation allowed) ----------------
__device__ __align__(16) float g_xlat[NROWS_X*LATD];   // x latents; rows 0..9/batch later overwritten with "enhanced"
__device__ __align__(16) float g_llat[NROWS_L*LATD];   // local latents
__device__ float g_qg[BB*NP*LATD];
__device__ float g_ql[BB*NP*LATD];
__device__ float g_pi[BB*NP];
__device__ float g_gw[BB];

__device__ __forceinline__ float warp_sum(float v) {
#pragma unroll
    for (int o = 16; o; o >>= 1) v += __shfl_xor_sync(0xffffffffu, v, o);
    return v;
}

// ---------------- Kernel 1: latent = quick_gelu(X @ Wd + bd) ----------------
// Block = 256 threads = 256 rows (one row per thread). K is chunked by KC and
// staged transposed in smem (conflict-free lane reads); Wd lives in smem and is
// read warp-uniform (broadcast LDS, ~free). 20 fp32 accumulators per thread.
#define KC 32
#define TILE_ROWS 256
#define XS_STRIDE (TILE_ROWS + 1)

__global__ void latent_kernel(const float* __restrict__ X,
                              const float* __restrict__ Wd,
                              const float* __restrict__ bd,
                              int nRows, int which) {
    extern __shared__ float smem[];
    float* wds = smem;                    // 768*20 floats
    float* xs  = smem + DIMD*LATD;        // KC * XS_STRIDE floats, layout xs[k][row]
    float* dst = which ? g_llat : g_xlat;

    int tid = threadIdx.x;
    // stage Wd (61440 B) once
    for (int i = tid; i < DIMD*LATD/4; i += 256)
        ((float4*)wds)[i] = ((const float4*)Wd)[i];

    int rowBase = blockIdx.x * TILE_ROWS;
    int myRow = rowBase + tid;

    float acc[LATD];
#pragma unroll
    for (int l = 0; l < LATD; l++) acc[l] = 0.f;

    for (int kc = 0; kc < DIMD; kc += KC) {
        __syncthreads();
        // cooperative load of 256 rows x KC cols, stored transposed
#pragma unroll
        for (int it = 0; it < (TILE_ROWS*KC/4)/256; it++) {
            int i = tid + it*256;
            int r  = i >> 3;     // KC/4 = 8 float4 per row
            int k4 = i & 7;
            float4 v = make_float4(0.f, 0.f, 0.f, 0.f);
            int gr = rowBase + r;
            if (gr < nRows) v = *(const float4*)(X + (size_t)gr*DIMD + kc + k4*4);
            xs[(k4*4+0)*XS_STRIDE + r] = v.x;
            xs[(k4*4+1)*XS_STRIDE + r] = v.y;
            xs[(k4*4+2)*XS_STRIDE + r] = v.z;
            xs[(k4*4+3)*XS_STRIDE + r] = v.w;
        }
        __syncthreads();
#pragma unroll 8
        for (int k = 0; k < KC; k++) {
            float xv = xs[k*XS_STRIDE + tid];
            const float4* wr = (const float4*)(wds + (kc + k)*LATD);
#pragma unroll
            for (int l4 = 0; l4 < 5; l4++) {
                float4 wv = wr[l4];
                acc[l4*4+0] = fmaf(xv, wv.x, acc[l4*4+0]);
                acc[l4*4+1] = fmaf(xv, wv.y, acc[l4*4+1]);
                acc[l4*4+2] = fmaf(xv, wv.z, acc[l4*4+2]);
                acc[l4*4+3] = fmaf(xv, wv.w, acc[l4*4+3]);
            }
        }
    }

    if (myRow < nRows) {
        float4 o4[5];
        float* ov = (float*)o4;
#pragma unroll
        for (int l = 0; l < LATD; l++) {
            float z = acc[l] + bd[l];
            ov[l] = z * (1.f / (1.f + __expf(-1.702f * z)));   // quick_gelu
        }
        float4* d4 = (float4*)(dst + (size_t)myRow*LATD);
#pragma unroll
        for (int q = 0; q < 5; q++) d4[q] = o4[q];
    }
}

// ---------------- Kernel 2: per-batch head math (1 warp per batch) ----------------
__global__ void head_kernel(const float* __restrict__ ln_c_g, const float* __restrict__ ln_c_b,
                            const float* __restrict__ Wc1,    const float* __restrict__ bc1,
                            const float* __restrict__ Wc2,    const float* __restrict__ bc2,
                            const float* __restrict__ ln_g_g, const float* __restrict__ ln_g_b,
                            const float* __restrict__ Wg,     const float* __restrict__ bg,
                            const float* __restrict__ Wgq,    const float* __restrict__ bgq,
                            const float* __restrict__ Wlq,    const float* __restrict__ blq) {
    int b = blockIdx.x;
    int lane = threadIdx.x;
    __shared__ float pr[NP*LATD];
    __shared__ float clsln[LATD];
    __shared__ float h[64];

    const float* base = g_xlat + (size_t)b*SEQ*LATD;
    for (int i = lane; i < NP*LATD; i += 32) pr[i] = base[i];

    float c = (lane < LATD) ? base[NP*LATD + lane] : 0.f;      // cls latent
    float mu = warp_sum(c) * (1.f/LATD);
    float d = (lane < LATD) ? (c - mu) : 0.f;
    float var = warp_sum(d*d) * (1.f/LATD);
    float rs = rsqrtf(var + 1e-5f);
    if (lane < LATD) clsln[lane] = d*rs*ln_c_g[lane] + ln_c_b[lane];
    __syncwarp();

    // h = gelu_exact(cls_ln @ Wc1 + bc1)
    for (int j = lane; j < 64; j += 32) {
        float s = bc1[j];
#pragma unroll
        for (int l = 0; l < LATD; l++) s = fmaf(clsln[l], Wc1[l*64 + j], s);
        h[j] = 0.5f*s*(1.f + erff(s*0.70710678118654752f));
    }
    __syncwarp();

    // prompt importance = sigmoid(h @ Wc2 + bc2)
    if (lane < NP) {
        float s = bc2[lane];
#pragma unroll
        for (int j = 0; j < 64; j++) s = fmaf(h[j], Wc2[j*NP + lane], s);
        g_pi[b*NP + lane] = 1.f/(1.f + __expf(-s));
    }

    // global weight = sigmoid(LN_g(cls) @ Wg + bg)
    float g2 = (lane < LATD) ? (d*rs*ln_g_g[lane] + ln_g_b[lane]) * Wg[lane] : 0.f;
    float sg = warp_sum(g2);
    if (lane == 0) g_gw[b] = 1.f/(1.f + __expf(-(sg + bg[0])));

    // q projections
    if (lane < LATD) {
        for (int p = 0; p < NP; p++) {
            float sq = bgq[lane], sl = blq[lane];
#pragma unroll
            for (int l = 0; l < LATD; l++) {
                float pv = pr[p*LATD + l];
                sq = fmaf(pv, Wgq[l*LATD + lane], sq);
                sl = fmaf(pv, Wlq[l*LATD + lane], sl);
            }
            g_qg[(b*NP + p)*LATD + lane] = sq;
            g_ql[(b*NP + p)*LATD + lane] = sl;
        }
    }
}

// ---------------- Kernel 3: attention + fuse + enhance (block per (b,p)) ----------------
__global__ void attn_kernel() {
    int blk = blockIdx.x;
    int b = blk / NP, p = blk % NP;
    int tid = threadIdx.x, lane = tid & 31, w = tid >> 5;

    __shared__ float q[LATD];
    __shared__ float sc[NTOK];
    __shared__ float red[8*21];
    __shared__ float tot[21];
    __shared__ float msh;
    __shared__ float ctx2[2][LATD];

    const float scale = 0.22360679774997896f;   // LATENT^-0.5

    for (int which = 0; which < 2; which++) {
        __syncthreads();
        if (tid < LATD) q[tid] = (which == 0 ? g_qg : g_ql)[(b*NP + p)*LATD + tid];
        __syncthreads();

        const float* tok = (which == 0)
            ? (g_xlat + ((size_t)b*SEQ + NP + 1)*LATD)      // global image latents
            : (g_llat + (size_t)b*NTOK*LATD);               // local latents

        // pass 1: scores + max
        float m = -1e30f;
        for (int i = tid; i < NTOK; i += 256) {
            const float4* t4 = (const float4*)(tok + (size_t)i*LATD);
            float s = 0.f;
#pragma unroll
            for (int l4 = 0; l4 < 5; l4++) {
                float4 tv = t4[l4];
                s += tv.x*q[l4*4+0] + tv.y*q[l4*4+1] + tv.z*q[l4*4+2] + tv.w*q[l4*4+3];
            }
            s *= scale;
            sc[i] = s;
            m = fmaxf(m, s);
        }
#pragma unroll
        for (int o = 16; o; o >>= 1) m = fmaxf(m, __shfl_xor_sync(0xffffffffu, m, o));
        if (lane == 0) red[w] = m;
        __syncthreads();
        if (tid == 0) {
            float mm = red[0];
#pragma unroll
            for (int i = 1; i < 8; i++) mm = fmaxf(mm, red[i]);
            msh = mm;
        }
        __syncthreads();
        m = msh;

        // pass 2: exp, sum, weighted accumulation
        float sum = 0.f;
        float acc[LATD];
#pragma unroll
        for (int l = 0; l < LATD; l++) acc[l] = 0.f;
        for (int i = tid; i < NTOK; i += 256) {
            float wgt = __expf(sc[i] - m);
            sum += wgt;
            const float4* t4 = (const float4*)(tok + (size_t)i*LATD);
#pragma unroll
            for (int l4 = 0; l4 < 5; l4++) {
                float4 tv = t4[l4];
                acc[l4*4+0] = fmaf(wgt, tv.x, acc[l4*4+0]);
                acc[l4*4+1] = fmaf(wgt, tv.y, acc[l4*4+1]);
                acc[l4*4+2] = fmaf(wgt, tv.z, acc[l4*4+2]);
                acc[l4*4+3] = fmaf(wgt, tv.w, acc[l4*4+3]);
            }
        }
        sum = warp_sum(sum);
#pragma unroll
        for (int l = 0; l < LATD; l++) acc[l] = warp_sum(acc[l]);
        if (lane == 0) {
            red[w*21] = sum;
#pragma unroll
            for (int l = 0; l < LATD; l++) red[w*21 + 1 + l] = acc[l];
        }
        __syncthreads();
        if (tid < 21) {
            float t = 0.f;
#pragma unroll
            for (int w2 = 0; w2 < 8; w2++) t += red[w2*21 + tid];
            tot[tid] = t;
        }
        __syncthreads();
        if (tid < LATD) ctx2[which][tid] = tot[tid+1] / tot[0];
    }
    __syncthreads();
    if (tid < LATD) {
        float g = g_gw[b], im = g_pi[b*NP + p];
        float e = im * (g*ctx2[0][tid] + (1.f - g)*ctx2[1][tid]);
        g_xlat[((size_t)b*SEQ + p)*LATD + tid] = e;     // overwrite prompt rows -> "combined"
    }
}

// ---------------- Kernel 4: out = combined @ Wu + bu ----------------
// Wu (20x768) held in 60 registers per thread (thread t owns cols t, t+256, t+512).
// Latent tile staged in smem, read broadcast. Fully coalesced 768-wide stores.
__global__ void out_kernel(const float* __restrict__ Wu,
                           const float* __restrict__ bu,
                           float* __restrict__ out) {
    __shared__ __align__(16) float ls[32*LATD];
    int tid = threadIdx.x;

    float wu[LATD][3];
#pragma unroll
    for (int l = 0; l < LATD; l++)
#pragma unroll
        for (int c = 0; c < 3; c++)
            wu[l][c] = Wu[l*DIMD + tid + c*256];
    float bu3[3];
#pragma unroll
    for (int c = 0; c < 3; c++) bu3[c] = bu[tid + c*256];

    int nTiles = (NROWS_X + 31) / 32;
    for (int t = blockIdx.x; t < nTiles; t += gridDim.x) {
        int rowBase = t * 32;
        __syncthreads();
#pragma unroll
        for (int it = 0; it < 3; it++) {
            int i = tid + it*256;
            if (i < 32*LATD && (size_t)rowBase*LATD + i < (size_t)NROWS_X*LATD)
                ls[i] = g_xlat[(size_t)rowBase*LATD + i];
        }
        __syncthreads();
        int rmax = min(32, NROWS_X - rowBase);
        for (int r = 0; r < rmax; r++) {
            float a0 = bu3[0], a1 = bu3[1], a2 = bu3[2];
            const float4* lr = (const float4*)(ls + r*LATD);
#pragma unroll
            for (int l4 = 0; l4 < 5; l4++) {
                float4 lv = lr[l4];
                a0 = fmaf(lv.x, wu[l4*4+0][0], a0); a1 = fmaf(lv.x, wu[l4*4+0][1], a1); a2 = fmaf(lv.x, wu[l4*4+0][2], a2);
                a0 = fmaf(lv.y, wu[l4*4+1][0], a0); a1 = fmaf(lv.y, wu[l4*4+1][1], a1); a2 = fmaf(lv.y, wu[l4*4+1][2], a2);
                a0 = fmaf(lv.z, wu[l4*4+2][0], a0); a1 = fmaf(lv.z, wu[l4*4+2][1], a1); a2 = fmaf(lv.z, wu[l4*4+2][2], a2);
                a0 = fmaf(lv.w, wu[l4*4+3][0], a0); a1 = fmaf(lv.w, wu[l4*4+3][1], a1); a2 = fmaf(lv.w, wu[l4*4+3][2], a2);
            }
            size_t o = (size_t)(rowBase + r)*DIMD + tid;
            out[o] = a0; out[o + 256] = a1; out[o + 512] = a2;
        }
    }
}

// ---------------- launch ----------------
extern "C" void kernel_launch(void* const* d_in, const int* in_sizes, int n_in,
                              void* d_out, int out_size) {
    const float* x      = (const float*)d_in[0];
    const float* loc    = (const float*)d_in[1];
    const float* Wd     = (const float*)d_in[2];
    const float* bd     = (const float*)d_in[3];
    const float* Wu     = (const float*)d_in[4];
    const float* bu     = (const float*)d_in[5];
    const float* Wgq    = (const float*)d_in[6];
    const float* bgq    = (const float*)d_in[7];
    const float* Wlq    = (const float*)d_in[8];
    const float* blq    = (const float*)d_in[9];
    const float* ln_c_g = (const float*)d_in[10];
    const float* ln_c_b = (const float*)d_in[11];
    const float* Wc1    = (const float*)d_in[12];
    const float* bc1    = (const float*)d_in[13];
    const float* Wc2    = (const float*)d_in[14];
    const float* bc2    = (const float*)d_in[15];
    const float* ln_g_g = (const float*)d_in[16];
    const float* ln_g_b = (const float*)d_in[17];
    const float* Wg     = (const float*)d_in[18];
    const float* bg     = (const float*)d_in[19];
    float* out = (float*)d_out;

    const size_t smemL = (size_t)(DIMD*LATD + KC*XS_STRIDE) * sizeof(float);
    cudaFuncSetAttribute(latent_kernel, cudaFuncAttributeMaxDynamicSharedMemorySize, (int)smemL);

    latent_kernel<<<(NROWS_X + TILE_ROWS - 1)/TILE_ROWS, 256, smemL>>>(x,   Wd, bd, NROWS_X, 0);
    latent_kernel<<<(NROWS_L + TILE_ROWS - 1)/TILE_ROWS, 256, smemL>>>(loc, Wd, bd, NROWS_L, 1);
    head_kernel<<<BB, 32>>>(ln_c_g, ln_c_b, Wc1, bc1, Wc2, bc2,
                            ln_g_g, ln_g_b, Wg, bg, Wgq, bgq, Wlq, blq);
    attn_kernel<<<BB*NP, 256>>>();
    out_kernel<<<592, 256>>>(Wu, bu, out);
}

// round 3
// speedup vs baseline: 1.0038x; 1.0038x over previous
#include <cuda_runtime.h>
#include <math.h>

#define BB 16
#define SEQ 4107
#define NTOK 4096
#define DIMD 768
#define LATD 20
#define NP 10
#define NROWS_X (BB*SEQ)
#define NROWS_L (BB*NTOK)

// ---------------- scratch (device globals: no allocation allowed) ----------------
__device__ __align__(16) float g_xlat[NROWS_X*LATD];   // x latents; rows 0..9/batch later overwritten with "enhanced"
__device__ __align__(16) float g_llat[NROWS_L*LATD];   // local latents
__device__ float g_qg[BB*NP*LATD];
__device__ float g_ql[BB*NP*LATD];
__device__ float g_pi[BB*NP];
__device__ float g_gw[BB];

__device__ __forceinline__ float warp_sum(float v) {
#pragma unroll
    for (int o = 16; o; o >>= 1) v += __shfl_xor_sync(0xffffffffu, v, o);
    return v;
}

// ---------------- Kernel 1: latent = quick_gelu(X @ Wd + bd) ----------------
// Block = 256 threads = 256 rows (one row per thread). K is chunked by KC and
// staged transposed in smem (conflict-free lane reads); Wd lives in smem and is
// read warp-uniform (broadcast LDS, ~free). 20 fp32 accumulators per thread.
#define KC 32
#define TILE_ROWS 256
#define XS_STRIDE (TILE_ROWS + 1)

__global__ void latent_kernel(const float* __restrict__ X,
                              const float* __restrict__ Wd,
                              const float* __restrict__ bd,
                              int nRows, int which) {
    extern __shared__ float smem[];
    float* wds = smem;                    // 768*20 floats
    float* xs  = smem + DIMD*LATD;        // KC * XS_STRIDE floats, layout xs[k][row]
    float* dst = which ? g_llat : g_xlat;

    int tid = threadIdx.x;
    // stage Wd (61440 B) once
    for (int i = tid; i < DIMD*LATD/4; i += 256)
        ((float4*)wds)[i] = ((const float4*)Wd)[i];

    int rowBase = blockIdx.x * TILE_ROWS;
    int myRow = rowBase + tid;

    float acc[LATD];
#pragma unroll
    for (int l = 0; l < LATD; l++) acc[l] = 0.f;

    for (int kc = 0; kc < DIMD; kc += KC) {
        __syncthreads();
        // cooperative load of 256 rows x KC cols, stored transposed
#pragma unroll
        for (int it = 0; it < (TILE_ROWS*KC/4)/256; it++) {
            int i = tid + it*256;
            int r  = i >> 3;     // KC/4 = 8 float4 per row
            int k4 = i & 7;
            float4 v = make_float4(0.f, 0.f, 0.f, 0.f);
            int gr = rowBase + r;
            if (gr < nRows) v = *(const float4*)(X + (size_t)gr*DIMD + kc + k4*4);
            xs[(k4*4+0)*XS_STRIDE + r] = v.x;
            xs[(k4*4+1)*XS_STRIDE + r] = v.y;
            xs[(k4*4+2)*XS_STRIDE + r] = v.z;
            xs[(k4*4+3)*XS_STRIDE + r] = v.w;
        }
        __syncthreads();
#pragma unroll 8
        for (int k = 0; k < KC; k++) {
            float xv = xs[k*XS_STRIDE + tid];
            const float4* wr = (const float4*)(wds + (kc + k)*LATD);
#pragma unroll
            for (int l4 = 0; l4 < 5; l4++) {
                float4 wv = wr[l4];
                acc[l4*4+0] = fmaf(xv, wv.x, acc[l4*4+0]);
                acc[l4*4+1] = fmaf(xv, wv.y, acc[l4*4+1]);
                acc[l4*4+2] = fmaf(xv, wv.z, acc[l4*4+2]);
                acc[l4*4+3] = fmaf(xv, wv.w, acc[l4*4+3]);
            }
        }
    }

    if (myRow < nRows) {
        float4 o4[5];
        float* ov = (float*)o4;
#pragma unroll
        for (int l = 0; l < LATD; l++) {
            float z = acc[l] + bd[l];
            ov[l] = z * (1.f / (1.f + __expf(-1.702f * z)));   // quick_gelu
        }
        float4* d4 = (float4*)(dst + (size_t)myRow*LATD);
#pragma unroll
        for (int q = 0; q < 5; q++) d4[q] = o4[q];
    }
}

// ---------------- Kernel 2: per-batch head math (1 warp per batch) ----------------
__global__ void head_kernel(const float* __restrict__ ln_c_g, const float* __restrict__ ln_c_b,
                            const float* __restrict__ Wc1,    const float* __restrict__ bc1,
                            const float* __restrict__ Wc2,    const float* __restrict__ bc2,
                            const float* __restrict__ ln_g_g, const float* __restrict__ ln_g_b,
                            const float* __restrict__ Wg,     const float* __restrict__ bg,
                            const float* __restrict__ Wgq,    const float* __restrict__ bgq,
                            const float* __restrict__ Wlq,    const float* __restrict__ blq) {
    int b = blockIdx.x;
    int lane = threadIdx.x;
    __shared__ float pr[NP*LATD];
    __shared__ float clsln[LATD];
    __shared__ float h[64];

    const float* base = g_xlat + (size_t)b*SEQ*LATD;
    for (int i = lane; i < NP*LATD; i += 32) pr[i] = base[i];

    float c = (lane < LATD) ? base[NP*LATD + lane] : 0.f;      // cls latent
    float mu = warp_sum(c) * (1.f/LATD);
    float d = (lane < LATD) ? (c - mu) : 0.f;
    float var = warp_sum(d*d) * (1.f/LATD);
    float rs = rsqrtf(var + 1e-5f);
    if (lane < LATD) clsln[lane] = d*rs*ln_c_g[lane] + ln_c_b[lane];
    __syncwarp();

    // h = gelu_exact(cls_ln @ Wc1 + bc1)
    for (int j = lane; j < 64; j += 32) {
        float s = bc1[j];
#pragma unroll
        for (int l = 0; l < LATD; l++) s = fmaf(clsln[l], Wc1[l*64 + j], s);
        h[j] = 0.5f*s*(1.f + erff(s*0.70710678118654752f));
    }
    __syncwarp();

    // prompt importance = sigmoid(h @ Wc2 + bc2)
    if (lane < NP) {
        float s = bc2[lane];
#pragma unroll
        for (int j = 0; j < 64; j++) s = fmaf(h[j], Wc2[j*NP + lane], s);
        g_pi[b*NP + lane] = 1.f/(1.f + __expf(-s));
    }

    // global weight = sigmoid(LN_g(cls) @ Wg + bg)
    float g2 = (lane < LATD) ? (d*rs*ln_g_g[lane] + ln_g_b[lane]) * Wg[lane] : 0.f;
    float sg = warp_sum(g2);
    if (lane == 0) g_gw[b] = 1.f/(1.f + __expf(-(sg + bg[0])));

    // q projections
    if (lane < LATD) {
        for (int p = 0; p < NP; p++) {
            float sq = bgq[lane], sl = blq[lane];
#pragma unroll
            for (int l = 0; l < LATD; l++) {
                float pv = pr[p*LATD + l];
                sq = fmaf(pv, Wgq[l*LATD + lane], sq);
                sl = fmaf(pv, Wlq[l*LATD + lane], sl);
            }
            g_qg[(b*NP + p)*LATD + lane] = sq;
            g_ql[(b*NP + p)*LATD + lane] = sl;
        }
    }
}

// ---------------- Kernel 3: attention + fuse + enhance (block per (b,p)) ----------------
__global__ void attn_kernel() {
    int blk = blockIdx.x;
    int b = blk / NP, p = blk % NP;
    int tid = threadIdx.x, lane = tid & 31, w = tid >> 5;

    __shared__ float q[LATD];
    __shared__ float sc[NTOK];
    __shared__ float red[8*21];
    __shared__ float tot[21];
    __shared__ float msh;
    __shared__ float ctx2[2][LATD];

    const float scale = 0.22360679774997896f;   // LATENT^-0.5

    for (int which = 0; which < 2; which++) {
        __syncthreads();
        if (tid < LATD) q[tid] = (which == 0 ? g_qg : g_ql)[(b*NP + p)*LATD + tid];
        __syncthreads();

        const float* tok = (which == 0)
            ? (g_xlat + ((size_t)b*SEQ + NP + 1)*LATD)      // global image latents
            : (g_llat + (size_t)b*NTOK*LATD);               // local latents

        // pass 1: scores + max
        float m = -1e30f;
        for (int i = tid; i < NTOK; i += 256) {
            const float4* t4 = (const float4*)(tok + (size_t)i*LATD);
            float s = 0.f;
#pragma unroll
            for (int l4 = 0; l4 < 5; l4++) {
                float4 tv = t4[l4];
                s += tv.x*q[l4*4+0] + tv.y*q[l4*4+1] + tv.z*q[l4*4+2] + tv.w*q[l4*4+3];
            }
            s *= scale;
            sc[i] = s;
            m = fmaxf(m, s);
        }
#pragma unroll
        for (int o = 16; o; o >>= 1) m = fmaxf(m, __shfl_xor_sync(0xffffffffu, m, o));
        if (lane == 0) red[w] = m;
        __syncthreads();
        if (tid == 0) {
            float mm = red[0];
#pragma unroll
            for (int i = 1; i < 8; i++) mm = fmaxf(mm, red[i]);
            msh = mm;
        }
        __syncthreads();
        m = msh;

        // pass 2: exp, sum, weighted accumulation
        float sum = 0.f;
        float acc[LATD];
#pragma unroll
        for (int l = 0; l < LATD; l++) acc[l] = 0.f;
        for (int i = tid; i < NTOK; i += 256) {
            float wgt = __expf(sc[i] - m);
            sum += wgt;
            const float4* t4 = (const float4*)(tok + (size_t)i*LATD);
#pragma unroll
            for (int l4 = 0; l4 < 5; l4++) {
                float4 tv = t4[l4];
                acc[l4*4+0] = fmaf(wgt, tv.x, acc[l4*4+0]);
                acc[l4*4+1] = fmaf(wgt, tv.y, acc[l4*4+1]);
                acc[l4*4+2] = fmaf(wgt, tv.z, acc[l4*4+2]);
                acc[l4*4+3] = fmaf(wgt, tv.w, acc[l4*4+3]);
            }
        }
        sum = warp_sum(sum);
#pragma unroll
        for (int l = 0; l < LATD; l++) acc[l] = warp_sum(acc[l]);
        if (lane == 0) {
            red[w*21] = sum;
#pragma unroll
            for (int l = 0; l < LATD; l++) red[w*21 + 1 + l] = acc[l];
        }
        __syncthreads();
        if (tid < 21) {
            float t = 0.f;
#pragma unroll
            for (int w2 = 0; w2 < 8; w2++) t += red[w2*21 + tid];
            tot[tid] = t;
        }
        __syncthreads();
        if (tid < LATD) ctx2[which][tid] = tot[tid+1] / tot[0];
    }
    __syncthreads();
    if (tid < LATD) {
        float g = g_gw[b], im = g_pi[b*NP + p];
        float e = im * (g*ctx2[0][tid] + (1.f - g)*ctx2[1][tid]);
        g_xlat[((size_t)b*SEQ + p)*LATD + tid] = e;     // overwrite prompt rows -> "combined"
    }
}

// ---------------- Kernel 4: out = combined @ Wu + bu ----------------
// Wu (20x768) held in 60 registers per thread (thread t owns cols t, t+256, t+512).
// Latent tile staged in smem, read broadcast. Fully coalesced 768-wide stores.
__global__ void out_kernel(const float* __restrict__ Wu,
                           const float* __restrict__ bu,
                           float* __restrict__ out) {
    __shared__ __align__(16) float ls[32*LATD];
    int tid = threadIdx.x;

    float wu[LATD][3];
#pragma unroll
    for (int l = 0; l < LATD; l++)
#pragma unroll
        for (int c = 0; c < 3; c++)
            wu[l][c] = Wu[l*DIMD + tid + c*256];
    float bu3[3];
#pragma unroll
    for (int c = 0; c < 3; c++) bu3[c] = bu[tid + c*256];

    int nTiles = (NROWS_X + 31) / 32;
    for (int t = blockIdx.x; t < nTiles; t += gridDim.x) {
        int rowBase = t * 32;
        __syncthreads();
#pragma unroll
        for (int it = 0; it < 3; it++) {
            int i = tid + it*256;
            if (i < 32*LATD && (size_t)rowBase*LATD + i < (size_t)NROWS_X*LATD)
                ls[i] = g_xlat[(size_t)rowBase*LATD + i];
        }
        __syncthreads();
        int rmax = min(32, NROWS_X - rowBase);
        for (int r = 0; r < rmax; r++) {
            float a0 = bu3[0], a1 = bu3[1], a2 = bu3[2];
            const float4* lr = (const float4*)(ls + r*LATD);
#pragma unroll
            for (int l4 = 0; l4 < 5; l4++) {
                float4 lv = lr[l4];
                a0 = fmaf(lv.x, wu[l4*4+0][0], a0); a1 = fmaf(lv.x, wu[l4*4+0][1], a1); a2 = fmaf(lv.x, wu[l4*4+0][2], a2);
                a0 = fmaf(lv.y, wu[l4*4+1][0], a0); a1 = fmaf(lv.y, wu[l4*4+1][1], a1); a2 = fmaf(lv.y, wu[l4*4+1][2], a2);
                a0 = fmaf(lv.z, wu[l4*4+2][0], a0); a1 = fmaf(lv.z, wu[l4*4+2][1], a1); a2 = fmaf(lv.z, wu[l4*4+2][2], a2);
                a0 = fmaf(lv.w, wu[l4*4+3][0], a0); a1 = fmaf(lv.w, wu[l4*4+3][1], a1); a2 = fmaf(lv.w, wu[l4*4+3][2], a2);
            }
            size_t o = (size_t)(rowBase + r)*DIMD + tid;
            out[o] = a0; out[o + 256] = a1; out[o + 512] = a2;
        }
    }
}

// ---------------- launch ----------------
extern "C" void kernel_launch(void* const* d_in, const int* in_sizes, int n_in,
                              void* d_out, int out_size) {
    const float* x      = (const float*)d_in[0];
    const float* loc    = (const float*)d_in[1];
    const float* Wd     = (const float*)d_in[2];
    const float* bd     = (const float*)d_in[3];
    const float* Wu     = (const float*)d_in[4];
    const float* bu     = (const float*)d_in[5];
    const float* Wgq    = (const float*)d_in[6];
    const float* bgq    = (const float*)d_in[7];
    const float* Wlq    = (const float*)d_in[8];
    const float* blq    = (const float*)d_in[9];
    const float* ln_c_g = (const float*)d_in[10];
    const float* ln_c_b = (const float*)d_in[11];
    const float* Wc1    = (const float*)d_in[12];
    const float* bc1    = (const float*)d_in[13];
    const float* Wc2    = (const float*)d_in[14];
    const float* bc2    = (const float*)d_in[15];
    const float* ln_g_g = (const float*)d_in[16];
    const float* ln_g_b = (const float*)d_in[17];
    const float* Wg     = (const float*)d_in[18];
    const float* bg     = (const float*)d_in[19];
    float* out = (float*)d_out;

    const size_t smemL = (size_t)(DIMD*LATD + KC*XS_STRIDE) * sizeof(float);
    cudaFuncSetAttribute(latent_kernel, cudaFuncAttributeMaxDynamicSharedMemorySize, (int)smemL);

    latent_kernel<<<(NROWS_X + TILE_ROWS - 1)/TILE_ROWS, 256, smemL>>>(x,   Wd, bd, NROWS_X, 0);
    latent_kernel<<<(NROWS_L + TILE_ROWS - 1)/TILE_ROWS, 256, smemL>>>(loc, Wd, bd, NROWS_L, 1);
    head_kernel<<<BB, 32>>>(ln_c_g, ln_c_b, Wc1, bc1, Wc2, bc2,
                            ln_g_g, ln_g_b, Wg, bg, Wgq, bgq, Wlq, blq);
    attn_kernel<<<BB*NP, 256>>>();
    out_kernel<<<592, 256>>>(Wu, bu, out);
}